// round 1
// baseline (speedup 1.0000x reference)
#include <cuda_runtime.h>
#include <math.h>

// ---------------- problem constants ----------------
#define Csz 512
#define NHh 8
#define CHd 64
#define Bsz 16

#define N0 3137
#define N1 785
#define N2 197
#define M0t (Bsz*N0)     // 50192
#define M1t (Bsz*N1)     // 12560
#define M2t (Bsz*N2)     // 3152
#define MTOT (M0t+M1t+M2t)

// ---------------- scratch (static device memory; no allocation) ----------------
__device__ float g_xp[(size_t)M0t*Csz];
__device__ float g_ln[(size_t)M0t*Csz];
__device__ float g_qkv[(size_t)M0t*3*Csz];
__device__ float g_conv[(size_t)Bsz*56*56*Csz];
__device__ float g_o[(size_t)M0t*Csz];
__device__ float g_kv[Bsz*NHh*64*64];
__device__ float g_cur[(size_t)MTOT*Csz];
__device__ float g_hid[(size_t)M0t*2048];

// resize tap tables: 6 (in,out) pairs, <=8 taps
__device__ int   g_rs_start[6][56];
__device__ int   g_rs_ntap[6][56];
__device__ float g_rs_w[6][56][8];

// ---------------- resize weight init (exact jax.image.resize bilinear, antialias=True) ----------------
__global__ void resize_init_kernel() {
    const int ins[6]  = {56,56,28,28,14,14};
    const int outs[6] = {28,14,56,14,56,28};
    int p = blockIdx.x;
    int o = threadIdx.x;
    int is = ins[p], os = outs[p];
    if (o >= os) return;
    float inv = (float)is / (float)os;          // inv_scale
    float ks  = inv > 1.f ? inv : 1.f;          // kernel_scale (antialias)
    float sample = (o + 0.5f) * inv - 0.5f;
    float wsum = 0.f;
    for (int i = 0; i < is; i++) {
        float w = 1.f - fabsf(sample - (float)i) / ks;
        if (w > 0.f) wsum += w;
    }
    int st = -1, cnt = 0;
    for (int i = 0; i < is; i++) {
        float w = 1.f - fabsf(sample - (float)i) / ks;
        if (w > 0.f) {
            if (st < 0) st = i;
            if (cnt < 8) g_rs_w[p][o][cnt] = w / wsum;
            cnt++;
        }
    }
    for (int j = cnt; j < 8; j++) g_rs_w[p][o][j] = 0.f;
    g_rs_start[p][o] = (st < 0) ? 0 : st;
    g_rs_ntap[p][o]  = (cnt > 8) ? 8 : cnt;
}

// ---------------- CPE: depthwise 3x3 conv + bias + residual, cls passthrough ----------------
__global__ void cpe_kernel(const float* __restrict__ x, const float* __restrict__ w,
                           const float* __restrict__ bias, float* __restrict__ xp,
                           int Nn, int H, int W) {
    size_t idx = (size_t)blockIdx.x * blockDim.x + threadIdx.x;
    size_t total = (size_t)Bsz * Nn * Csz;
    if (idx >= total) return;
    int c = (int)(idx & (Csz-1));
    size_t t = idx >> 9;
    int n = (int)(t % Nn);
    int b = (int)(t / Nn);
    const float* xb = x + (size_t)b * Nn * Csz;
    float val = xb[(size_t)n * Csz + c];
    if (n == 0) { xp[idx] = val; return; }
    int p = n - 1, y = p / W, xx = p % W;
    float acc = bias[c] + val;
    const float* wc = w + c * 9;
    #pragma unroll
    for (int dy = -1; dy <= 1; dy++) {
        int yy = y + dy;
        if ((unsigned)yy >= (unsigned)H) continue;
        #pragma unroll
        for (int dx = -1; dx <= 1; dx++) {
            int xc = xx + dx;
            if ((unsigned)xc >= (unsigned)W) continue;
            acc += wc[(dy+1)*3 + (dx+1)] * xb[(size_t)(1 + yy*W + xc) * Csz + c];
        }
    }
    xp[idx] = acc;
}

// ---------------- LayerNorm over C=512 ----------------
__global__ void ln_kernel(const float* __restrict__ in, float* __restrict__ out,
                          const float* __restrict__ g, const float* __restrict__ beta) {
    size_t row = blockIdx.x;
    const float4* p = (const float4*)(in + row * Csz);
    float4 v = p[threadIdx.x];
    float s = v.x + v.y + v.z + v.w;
    #pragma unroll
    for (int o = 16; o; o >>= 1) s += __shfl_xor_sync(0xffffffffu, s, o);
    __shared__ float sh[4];
    __shared__ float sh2[4];
    if ((threadIdx.x & 31) == 0) sh[threadIdx.x >> 5] = s;
    __syncthreads();
    float mean = (sh[0] + sh[1] + sh[2] + sh[3]) * (1.f/512.f);
    float dx = v.x - mean, dy = v.y - mean, dz = v.z - mean, dw = v.w - mean;
    float q = dx*dx + dy*dy + dz*dz + dw*dw;
    #pragma unroll
    for (int o = 16; o; o >>= 1) q += __shfl_xor_sync(0xffffffffu, q, o);
    if ((threadIdx.x & 31) == 0) sh2[threadIdx.x >> 5] = q;
    __syncthreads();
    float var = (sh2[0] + sh2[1] + sh2[2] + sh2[3]) * (1.f/512.f);
    float rs = rsqrtf(var + 1e-5f);
    float4 gg = ((const float4*)g)[threadIdx.x];
    float4 bb = ((const float4*)beta)[threadIdx.x];
    float4 r;
    r.x = dx * rs * gg.x + bb.x;
    r.y = dy * rs * gg.y + bb.y;
    r.z = dz * rs * gg.z + bb.z;
    r.w = dw * rs * gg.w + bb.w;
    ((float4*)(out + row * Csz))[threadIdx.x] = r;
}

// ---------------- tiled SGEMM 128x128x8, 8x8 microtile, fused epilogues ----------------
// epi: 0 = store, 1 = +bias store, 2 = +bias gelu store, 3 = out += acc + bias (residual)
__global__ __launch_bounds__(256) void gemm128(const float* __restrict__ A, const float* __restrict__ B,
                        float* __restrict__ Co, int M, int N, int K,
                        const float* __restrict__ bias, int epi) {
    __shared__ float As[8][128];
    __shared__ float Bs[8][128];
    int tid = threadIdx.x;
    int bm = blockIdx.y * 128, bn = blockIdx.x * 128;
    int tx = (tid & 15) * 8, ty = (tid >> 4) * 8;
    float acc[8][8];
    #pragma unroll
    for (int i = 0; i < 8; i++)
        #pragma unroll
        for (int j = 0; j < 8; j++) acc[i][j] = 0.f;

    int ar = tid >> 1, ak = (tid & 1) * 4;
    int br = tid >> 5, bc = (tid & 31) * 4;

    for (int k0 = 0; k0 < K; k0 += 8) {
        float4 av = make_float4(0.f,0.f,0.f,0.f);
        if (bm + ar < M) av = *(const float4*)(A + (size_t)(bm + ar) * K + k0 + ak);
        float4 bv = *(const float4*)(B + (size_t)(k0 + br) * N + bn + bc);
        __syncthreads();
        As[ak+0][ar] = av.x; As[ak+1][ar] = av.y; As[ak+2][ar] = av.z; As[ak+3][ar] = av.w;
        *(float4*)&Bs[br][bc] = bv;
        __syncthreads();
        #pragma unroll
        for (int kk = 0; kk < 8; kk++) {
            float a[8], b[8];
            #pragma unroll
            for (int i = 0; i < 8; i++) a[i] = As[kk][ty + i];
            #pragma unroll
            for (int j = 0; j < 8; j++) b[j] = Bs[kk][tx + j];
            #pragma unroll
            for (int i = 0; i < 8; i++)
                #pragma unroll
                for (int j = 0; j < 8; j++) acc[i][j] += a[i] * b[j];
        }
    }
    #pragma unroll
    for (int i = 0; i < 8; i++) {
        int row = bm + ty + i;
        if (row >= M) continue;
        #pragma unroll
        for (int j = 0; j < 8; j++) {
            int col = bn + tx + j;
            float v = acc[i][j];
            if (epi >= 1) v += bias[col];
            if (epi == 2) v = 0.5f * v * (1.f + erff(v * 0.70710678118654752f));
            size_t o = (size_t)row * N + col;
            if (epi == 3) Co[o] += v; else Co[o] = v;
        }
    }
}

// ---------------- softmax(K over N) fused with kv = ksm^T @ v per (b,h) ----------------
__global__ void kv_kernel(const float* __restrict__ qkv, float* __restrict__ kvout, int Nn) {
    int bh = blockIdx.x;
    int b = bh >> 3, h = bh & 7;
    int tid = threadIdx.x, ch = tid & 63, grp = tid >> 6;
    const float* base = qkv + (size_t)b * Nn * 1536 + h * 64;
    __shared__ float red[4][64];

    float m = -1e30f;
    for (int n = grp; n < Nn; n += 4) m = fmaxf(m, base[(size_t)n * 1536 + 512 + ch]);
    red[grp][ch] = m;
    __syncthreads();
    float mx = fmaxf(fmaxf(red[0][ch], red[1][ch]), fmaxf(red[2][ch], red[3][ch]));
    __syncthreads();
    float s = 0.f;
    for (int n = grp; n < Nn; n += 4) s += expf(base[(size_t)n * 1536 + 512 + ch] - mx);
    red[grp][ch] = s;
    __syncthreads();
    float inv = 1.f / (red[0][ch] + red[1][ch] + red[2][ch] + red[3][ch]);

    float acc[16];
    #pragma unroll
    for (int i = 0; i < 16; i++) acc[i] = 0.f;
    int ka = grp * 16, cv = ch;
    __shared__ float ws[4][64];
    __shared__ float vs[4][64];
    int nIter = (Nn + 3) >> 2;
    for (int it = 0; it < nIter; it++) {
        int n = it * 4 + grp;
        float kw = 0.f, vv = 0.f;
        if (n < Nn) {
            kw = expf(base[(size_t)n * 1536 + 512 + ch] - mx) * inv;
            vv = base[(size_t)n * 1536 + 1024 + ch];
        }
        __syncthreads();
        ws[grp][ch] = kw; vs[grp][ch] = vv;
        __syncthreads();
        float v0 = vs[0][cv], v1 = vs[1][cv], v2 = vs[2][cv], v3 = vs[3][cv];
        #pragma unroll
        for (int i = 0; i < 16; i++)
            acc[i] += ws[0][ka+i]*v0 + ws[1][ka+i]*v1 + ws[2][ka+i]*v2 + ws[3][ka+i]*v3;
    }
    float* kvp = kvout + ((size_t)bh * 64 + ka) * 64 + cv;
    #pragma unroll
    for (int i = 0; i < 16; i++) kvp[(size_t)i * 64] = acc[i];
}

// ---------------- CRPE depthwise conv on V image (3x3 / 5x5 / 7x7 per head group) ----------------
__global__ void crpe_conv_kernel(const float* __restrict__ qkv, float* __restrict__ convout,
                                 const float* __restrict__ w3, const float* __restrict__ b3,
                                 const float* __restrict__ w5, const float* __restrict__ b5,
                                 const float* __restrict__ w7, const float* __restrict__ b7,
                                 int Nn, int H, int W) {
    size_t idx = (size_t)blockIdx.x * blockDim.x + threadIdx.x;
    int HW = H * W;
    size_t total = (size_t)Bsz * HW * Csz;
    if (idx >= total) return;
    int c = (int)(idx & (Csz-1));
    size_t t = idx >> 9;
    int p = (int)(t % HW);
    int b = (int)(t / HW);
    int h = c >> 6;
    int ks; const float* wp; float acc;
    if (h < 2)      { ks = 3; wp = w3 + c * 9;          acc = b3[c];       }
    else if (h < 5) { ks = 5; wp = w5 + (c - 128) * 25; acc = b5[c - 128]; }
    else            { ks = 7; wp = w7 + (c - 320) * 49; acc = b7[c - 320]; }
    int y = p / W, x = p % W, r = ks >> 1;
    const float* vbase = qkv + (size_t)b * Nn * 1536 + 1024 + c;
    for (int dy = -r; dy <= r; dy++) {
        int yy = y + dy;
        if ((unsigned)yy >= (unsigned)H) continue;
        for (int dx = -r; dx <= r; dx++) {
            int xc = x + dx;
            if ((unsigned)xc >= (unsigned)W) continue;
            acc += wp[(dy+r)*ks + (dx+r)] * vbase[(size_t)(1 + yy*W + xc) * 1536];
        }
    }
    convout[idx] = acc;
}

// ---------------- fa = q @ kv, o = SCALE*fa + q*conv (crpe) ----------------
__global__ void fa_kernel(const float* __restrict__ qkv, const float* __restrict__ kvbuf,
                          const float* __restrict__ conv, float* __restrict__ obuf,
                          int Nn, int HW) {
    int bh = blockIdx.x;
    int b = bh >> 3, h = bh & 7;
    int n0 = blockIdx.y * 32;
    int tid = threadIdx.x, cv = tid & 63, yg = tid >> 6;
    __shared__ float kvs[64][65];
    __shared__ float qs[4][64];
    const float* kvsrc = kvbuf + (size_t)bh * 4096;
    for (int t = tid; t < 4096; t += 256) kvs[t >> 6][t & 63] = kvsrc[t];
    for (int it = 0; it < 8; it++) {
        int n = n0 + it * 4 + yg;
        bool ok = n < Nn;
        __syncthreads();
        qs[yg][cv] = ok ? qkv[((size_t)b * Nn + n) * 1536 + h * 64 + cv] : 0.f;
        __syncthreads();
        if (!ok) continue;
        float acc = 0.f;
        #pragma unroll
        for (int k = 0; k < 64; k++) acc += qs[yg][k] * kvs[k][cv];
        float res = 0.125f * acc;   // SCALE = 64^-0.5
        if (n > 0) res += qs[yg][cv] * conv[((size_t)b * HW + (n - 1)) * Csz + h * 64 + cv];
        obuf[((size_t)b * Nn + n) * Csz + h * 64 + cv] = res;
    }
}

// ---------------- cross-scale combine: x = feats + cur_i + interp(cur_A) + interp(cur_B) ----------------
__global__ void combine_kernel(const float* __restrict__ feats, const float* __restrict__ curi,
                               const float* __restrict__ curA, const float* __restrict__ curB,
                               float* __restrict__ xout,
                               int Nout, int Wout,
                               int NA, int WA, int pA,
                               int NB, int WB, int pB) {
    size_t idx = (size_t)blockIdx.x * blockDim.x + threadIdx.x;
    size_t total = (size_t)Bsz * Nout * Csz;
    if (idx >= total) return;
    int c = (int)(idx & (Csz-1));
    size_t t = idx >> 9;
    int n = (int)(t % Nout);
    int b = (int)(t / Nout);
    float val = feats[idx] + curi[idx];
    if (n == 0) {
        val += curA[(size_t)b * NA * Csz + c] + curB[(size_t)b * NB * Csz + c];
    } else {
        int p = n - 1, oy = p / Wout, ox = p % Wout;
        {
            int sy = g_rs_start[pA][oy], ny = g_rs_ntap[pA][oy];
            int sx = g_rs_start[pA][ox], nx = g_rs_ntap[pA][ox];
            float accy = 0.f;
            for (int ty = 0; ty < ny; ty++) {
                const float* rp = curA + ((size_t)b * NA + 1 + (size_t)(sy + ty) * WA + sx) * Csz + c;
                float a2 = 0.f;
                for (int txi = 0; txi < nx; txi++) a2 += g_rs_w[pA][ox][txi] * rp[(size_t)txi * Csz];
                accy += g_rs_w[pA][oy][ty] * a2;
            }
            val += accy;
        }
        {
            int sy = g_rs_start[pB][oy], ny = g_rs_ntap[pB][oy];
            int sx = g_rs_start[pB][ox], nx = g_rs_ntap[pB][ox];
            float accy = 0.f;
            for (int ty = 0; ty < ny; ty++) {
                const float* rp = curB + ((size_t)b * NB + 1 + (size_t)(sy + ty) * WB + sx) * Csz + c;
                float a2 = 0.f;
                for (int txi = 0; txi < nx; txi++) a2 += g_rs_w[pB][ox][txi] * rp[(size_t)txi * Csz];
                accy += g_rs_w[pB][oy][ty] * a2;
            }
            val += accy;
        }
    }
    xout[idx] = val;
}

// ---------------- host orchestration ----------------
extern "C" void kernel_launch(void* const* d_in, const int* in_sizes, int n_in,
                              void* d_out, int out_size) {
    const float* x[3] = {(const float*)d_in[0], (const float*)d_in[1], (const float*)d_in[2]};
    const float* cpe_w  = (const float*)d_in[3];
    const float* cpe_b  = (const float*)d_in[4];
    const float* n1_g   = (const float*)d_in[5];
    const float* n1_b   = (const float*)d_in[6];
    const float* n2_g   = (const float*)d_in[7];
    const float* n2_b   = (const float*)d_in[8];
    const float* qkv_w  = (const float*)d_in[9];
    const float* proj_w = (const float*)d_in[10];
    const float* proj_b = (const float*)d_in[11];
    const float* w3 = (const float*)d_in[12];
    const float* b3 = (const float*)d_in[13];
    const float* w5 = (const float*)d_in[14];
    const float* b5 = (const float*)d_in[15];
    const float* w7 = (const float*)d_in[16];
    const float* b7 = (const float*)d_in[17];
    const float* fc1_w = (const float*)d_in[18];
    const float* fc1_b = (const float*)d_in[19];
    const float* fc2_w = (const float*)d_in[20];
    const float* fc2_b = (const float*)d_in[21];
    float* out = (float*)d_out;

    float *xp, *ln, *qkv, *conv, *obuf, *kv, *cur, *hid;
    cudaGetSymbolAddress((void**)&xp,  g_xp);
    cudaGetSymbolAddress((void**)&ln,  g_ln);
    cudaGetSymbolAddress((void**)&qkv, g_qkv);
    cudaGetSymbolAddress((void**)&conv,g_conv);
    cudaGetSymbolAddress((void**)&obuf,g_o);
    cudaGetSymbolAddress((void**)&kv,  g_kv);
    cudaGetSymbolAddress((void**)&cur, g_cur);
    cudaGetSymbolAddress((void**)&hid, g_hid);

    const int Hh[3] = {56, 28, 14};
    const int Nn[3] = {N0, N1, N2};
    const int Mm[3] = {M0t, M1t, M2t};
    const size_t curoff[3] = {0, (size_t)M0t * Csz, (size_t)(M0t + M1t) * Csz};
    // resize pair indices: pairIdx[src j][dst i]
    // pairs: 0:(56->28) 1:(56->14) 2:(28->56) 3:(28->14) 4:(14->56) 5:(14->28)
    const int pairIdx[3][3] = { {-1, 0, 1}, {2, -1, 3}, {4, 5, -1} };

    resize_init_kernel<<<6, 64>>>();

    // --------- phase A: per-branch attention -> cur ---------
    for (int i = 0; i < 3; i++) {
        int H = Hh[i], W = Hh[i], Ni = Nn[i], Mi = Mm[i], HW = H * W;
        size_t totalMC = (size_t)Mi * Csz;
        int blocks = (int)((totalMC + 255) / 256);

        cpe_kernel<<<blocks, 256>>>(x[i], cpe_w + (size_t)i * Csz * 9, cpe_b + i * Csz,
                                    xp, Ni, H, W);
        ln_kernel<<<Mi, 128>>>(xp, ln, n1_g + i * Csz, n1_b + i * Csz);

        dim3 gq(1536 / 128, (Mi + 127) / 128);
        gemm128<<<gq, 256>>>(ln, qkv_w + (size_t)i * Csz * 1536, qkv,
                             Mi, 1536, Csz, nullptr, 0);

        kv_kernel<<<Bsz * NHh, 256>>>(qkv, kv, Ni);

        size_t totConv = (size_t)Bsz * HW * Csz;
        crpe_conv_kernel<<<(int)((totConv + 255) / 256), 256>>>(
            qkv, conv,
            w3 + (size_t)i * 128 * 9,  b3 + i * 128,
            w5 + (size_t)i * 192 * 25, b5 + i * 192,
            w7 + (size_t)i * 192 * 49, b7 + i * 192,
            Ni, H, W);

        dim3 gfa(Bsz * NHh, (Ni + 31) / 32);
        fa_kernel<<<gfa, 256>>>(qkv, kv, conv, obuf, Ni, HW);

        dim3 gp(Csz / 128, (Mi + 127) / 128);
        gemm128<<<gp, 256>>>(obuf, proj_w + (size_t)i * Csz * Csz, cur + curoff[i],
                             Mi, Csz, Csz, proj_b + i * Csz, 1);
    }

    // --------- phase B: cross-scale combine + MLP ---------
    for (int i = 0; i < 3; i++) {
        int Ni = Nn[i], Mi = Mm[i], W = Hh[i];
        int jA = (i == 0) ? 1 : 0;
        int jB = (i == 2) ? 1 : 2;
        size_t totalMC = (size_t)Mi * Csz;
        int blocks = (int)((totalMC + 255) / 256);
        size_t outoff = curoff[i];   // same layout as cur

        combine_kernel<<<blocks, 256>>>(x[i], cur + curoff[i],
                                        cur + curoff[jA], cur + curoff[jB],
                                        out + outoff,
                                        Ni, W,
                                        Nn[jA], Hh[jA], pairIdx[jA][i],
                                        Nn[jB], Hh[jB], pairIdx[jB][i]);

        ln_kernel<<<Mi, 128>>>(out + outoff, ln, n2_g + i * Csz, n2_b + i * Csz);

        dim3 g1(2048 / 128, (Mi + 127) / 128);
        gemm128<<<g1, 256>>>(ln, fc1_w, hid, Mi, 2048, Csz, fc1_b, 2);

        dim3 g2(Csz / 128, (Mi + 127) / 128);
        gemm128<<<g2, 256>>>(hid, fc2_w, out + outoff, Mi, Csz, 2048, fc2_b, 3);
    }
}

// round 2
// speedup vs baseline: 2.2083x; 2.2083x over previous
#include <cuda_runtime.h>
#include <cstdint>
#include <math.h>

// ---------------- problem constants ----------------
#define Csz 512
#define NHh 8
#define CHd 64
#define Bsz 16

#define N0 3137
#define N1 785
#define N2 197
#define M0t (Bsz*N0)     // 50192
#define M1t (Bsz*N1)     // 12560
#define M2t (Bsz*N2)     // 3152
#define MTOT (M0t+M1t+M2t)

// ---------------- scratch (static device memory; no allocation) ----------------
__device__ float g_xp[(size_t)M0t*Csz];
__device__ float g_ln[(size_t)M0t*Csz];
__device__ float g_qkv[(size_t)M0t*3*Csz];
__device__ float g_conv[(size_t)Bsz*56*56*Csz];
__device__ float g_o[(size_t)M0t*Csz];
__device__ float g_kv[Bsz*NHh*64*64];
__device__ float g_cur[(size_t)MTOT*Csz];
__device__ float g_hid[(size_t)M0t*2048];
__device__ float g_wbuf[5242880];   // tf32-rounded weights: wq | wp | w1 | w2

// resize tap tables: 6 (in,out) pairs, <=8 taps
__device__ int   g_rs_start[6][56];
__device__ int   g_rs_ntap[6][56];
__device__ float g_rs_w[6][56][8];

// ---------------- helpers ----------------
__device__ __forceinline__ float rtf32(float x) {
    uint32_t u;
    asm("cvt.rna.tf32.f32 %0, %1;" : "=r"(u) : "f"(x));
    return __uint_as_float(u);
}

__device__ __forceinline__ void cp16(void* dst, const void* src) {
    uint32_t d = (uint32_t)__cvta_generic_to_shared(dst);
    asm volatile("cp.async.cg.shared.global [%0], [%1], 16;" :: "r"(d), "l"(src));
}

__device__ __forceinline__ void mma_tf32(float* c, const uint32_t* a, const uint32_t* b) {
    asm volatile(
        "mma.sync.aligned.m16n8k8.row.col.f32.tf32.tf32.f32 "
        "{%0,%1,%2,%3}, {%4,%5,%6,%7}, {%8,%9}, {%0,%1,%2,%3};"
        : "+f"(c[0]), "+f"(c[1]), "+f"(c[2]), "+f"(c[3])
        : "r"(a[0]), "r"(a[1]), "r"(a[2]), "r"(a[3]), "r"(b[0]), "r"(b[1]));
}

// ---------------- weight rounding ----------------
__global__ void round_tf32_kernel(const float* __restrict__ in, float* __restrict__ out, int n) {
    int i = blockIdx.x * blockDim.x + threadIdx.x;
    if (i < n) out[i] = rtf32(in[i]);
}

// ---------------- resize weight init (exact jax.image.resize bilinear, antialias=True) ----------------
__global__ void resize_init_kernel() {
    const int ins[6]  = {56,56,28,28,14,14};
    const int outs[6] = {28,14,56,14,56,28};
    int p = blockIdx.x;
    int o = threadIdx.x;
    int is = ins[p], os = outs[p];
    if (o >= os) return;
    float inv = (float)is / (float)os;
    float ks  = inv > 1.f ? inv : 1.f;
    float sample = (o + 0.5f) * inv - 0.5f;
    float wsum = 0.f;
    for (int i = 0; i < is; i++) {
        float w = 1.f - fabsf(sample - (float)i) / ks;
        if (w > 0.f) wsum += w;
    }
    int st = -1, cnt = 0;
    for (int i = 0; i < is; i++) {
        float w = 1.f - fabsf(sample - (float)i) / ks;
        if (w > 0.f) {
            if (st < 0) st = i;
            if (cnt < 8) g_rs_w[p][o][cnt] = w / wsum;
            cnt++;
        }
    }
    for (int j = cnt; j < 8; j++) g_rs_w[p][o][j] = 0.f;
    g_rs_start[p][o] = (st < 0) ? 0 : st;
    g_rs_ntap[p][o]  = (cnt > 8) ? 8 : cnt;
}

// ---------------- CPE: depthwise 3x3 conv + bias + residual, cls passthrough ----------------
__global__ void cpe_kernel(const float* __restrict__ x, const float* __restrict__ w,
                           const float* __restrict__ bias, float* __restrict__ xp,
                           int Nn, int H, int W) {
    size_t idx = (size_t)blockIdx.x * blockDim.x + threadIdx.x;
    size_t total = (size_t)Bsz * Nn * Csz;
    if (idx >= total) return;
    int c = (int)(idx & (Csz-1));
    size_t t = idx >> 9;
    int n = (int)(t % Nn);
    int b = (int)(t / Nn);
    const float* xb = x + (size_t)b * Nn * Csz;
    float val = xb[(size_t)n * Csz + c];
    if (n == 0) { xp[idx] = val; return; }
    int p = n - 1, y = p / W, xx = p % W;
    float acc = bias[c] + val;
    const float* wc = w + c * 9;
    #pragma unroll
    for (int dy = -1; dy <= 1; dy++) {
        int yy = y + dy;
        if ((unsigned)yy >= (unsigned)H) continue;
        #pragma unroll
        for (int dx = -1; dx <= 1; dx++) {
            int xc = xx + dx;
            if ((unsigned)xc >= (unsigned)W) continue;
            acc += wc[(dy+1)*3 + (dx+1)] * xb[(size_t)(1 + yy*W + xc) * Csz + c];
        }
    }
    xp[idx] = acc;
}

// ---------------- LayerNorm over C=512 (output rounded to tf32 — always feeds a GEMM) ----------------
__global__ void ln_kernel(const float* __restrict__ in, float* __restrict__ out,
                          const float* __restrict__ g, const float* __restrict__ beta) {
    size_t row = blockIdx.x;
    const float4* p = (const float4*)(in + row * Csz);
    float4 v = p[threadIdx.x];
    float s = v.x + v.y + v.z + v.w;
    #pragma unroll
    for (int o = 16; o; o >>= 1) s += __shfl_xor_sync(0xffffffffu, s, o);
    __shared__ float sh[4];
    __shared__ float sh2[4];
    if ((threadIdx.x & 31) == 0) sh[threadIdx.x >> 5] = s;
    __syncthreads();
    float mean = (sh[0] + sh[1] + sh[2] + sh[3]) * (1.f/512.f);
    float dx = v.x - mean, dy = v.y - mean, dz = v.z - mean, dw = v.w - mean;
    float q = dx*dx + dy*dy + dz*dz + dw*dw;
    #pragma unroll
    for (int o = 16; o; o >>= 1) q += __shfl_xor_sync(0xffffffffu, q, o);
    if ((threadIdx.x & 31) == 0) sh2[threadIdx.x >> 5] = q;
    __syncthreads();
    float var = (sh2[0] + sh2[1] + sh2[2] + sh2[3]) * (1.f/512.f);
    float rs = rsqrtf(var + 1e-5f);
    float4 gg = ((const float4*)g)[threadIdx.x];
    float4 bb = ((const float4*)beta)[threadIdx.x];
    float4 r;
    r.x = rtf32(dx * rs * gg.x + bb.x);
    r.y = rtf32(dy * rs * gg.y + bb.y);
    r.z = rtf32(dz * rs * gg.z + bb.z);
    r.w = rtf32(dw * rs * gg.w + bb.w);
    ((float4*)(out + row * Csz))[threadIdx.x] = r;
}

// ---------------- tensor-core tf32 GEMM 128x128x32, mma.sync m16n8k8 ----------------
// epi: 0 = store, 1 = +bias store, 2 = +bias gelu store(rounded tf32), 3 = out += acc + bias
#define AST 36
#define BST 136
__global__ __launch_bounds__(256) void gemm_tc(
        const float* __restrict__ A, const float* __restrict__ B,
        float* __restrict__ Co, int M, int N, int K,
        const float* __restrict__ bias, int epi) {
    extern __shared__ float smbuf[];
    float* As = smbuf;                 // [2][128*AST]
    float* Bs = smbuf + 2 * 128 * AST; // [2][32*BST]
    int tid = threadIdx.x;
    int bm = blockIdx.y * 128, bn = blockIdx.x * 128;
    int wid = tid >> 5, lane = tid & 31;
    int g = lane >> 2, t = lane & 3;
    int warpM = wid >> 2, warpN = wid & 3;
    int mBase = warpM * 64, nBase = warpN * 32;

    float acc[4][4][4];
    #pragma unroll
    for (int i = 0; i < 4; i++)
        #pragma unroll
        for (int j = 0; j < 4; j++)
            #pragma unroll
            for (int r = 0; r < 4; r++) acc[i][j][r] = 0.f;

    int KT = K >> 5;

    auto issue = [&](int stage, int kt) {
        float* as = As + stage * 128 * AST;
        float* bs = Bs + stage * 32 * BST;
        #pragma unroll
        for (int q = 0; q < 4; q++) {
            int c = tid + q * 256;
            int r = c >> 3, k4 = (c & 7) << 2;
            int rr = bm + r; if (rr > M - 1) rr = M - 1;
            cp16(as + r * AST + k4, A + (size_t)rr * K + kt * 32 + k4);
        }
        #pragma unroll
        for (int q = 0; q < 4; q++) {
            int c = tid + q * 256;
            int r = c >> 5, n4 = (c & 31) << 2;
            cp16(bs + r * BST + n4, B + (size_t)(kt * 32 + r) * N + bn + n4);
        }
        asm volatile("cp.async.commit_group;");
    };

    auto compute = [&](int stage) {
        const float* as = As + stage * 128 * AST;
        const float* bs = Bs + stage * 32 * BST;
        #pragma unroll
        for (int ks = 0; ks < 4; ks++) {
            int k0 = ks * 8 + t;
            uint32_t af[4][4], bf[4][2];
            #pragma unroll
            for (int i = 0; i < 4; i++) {
                const float* ap = as + (mBase + 16 * i + g) * AST;
                af[i][0] = __float_as_uint(ap[k0]);
                af[i][1] = __float_as_uint(ap[8 * AST + k0]);
                af[i][2] = __float_as_uint(ap[k0 + 4]);
                af[i][3] = __float_as_uint(ap[8 * AST + k0 + 4]);
            }
            #pragma unroll
            for (int j = 0; j < 4; j++) {
                const float* bp = bs + k0 * BST + nBase + 8 * j + g;
                bf[j][0] = __float_as_uint(bp[0]);
                bf[j][1] = __float_as_uint(bp[4 * BST]);
            }
            #pragma unroll
            for (int i = 0; i < 4; i++)
                #pragma unroll
                for (int j = 0; j < 4; j++)
                    mma_tf32(acc[i][j], af[i], bf[j]);
        }
    };

    issue(0, 0);
    for (int kt = 0; kt < KT; kt++) {
        if (kt + 1 < KT) {
            issue((kt + 1) & 1, kt + 1);
            asm volatile("cp.async.wait_group 1;");
        } else {
            asm volatile("cp.async.wait_group 0;");
        }
        __syncthreads();
        compute(kt & 1);
        __syncthreads();
    }

    // epilogue
    #pragma unroll
    for (int i = 0; i < 4; i++) {
        #pragma unroll
        for (int half = 0; half < 2; half++) {
            int row = bm + mBase + 16 * i + g + half * 8;
            if (row >= M) continue;
            #pragma unroll
            for (int j = 0; j < 4; j++) {
                int col = bn + nBase + 8 * j + 2 * t;
                float v0 = acc[i][j][half * 2 + 0];
                float v1 = acc[i][j][half * 2 + 1];
                if (epi >= 1) { v0 += bias[col]; v1 += bias[col + 1]; }
                if (epi == 2) {
                    v0 = rtf32(0.5f * v0 * (1.f + erff(v0 * 0.70710678118654752f)));
                    v1 = rtf32(0.5f * v1 * (1.f + erff(v1 * 0.70710678118654752f)));
                }
                float2* p = (float2*)(Co + (size_t)row * N + col);
                if (epi == 3) { float2 o = *p; o.x += v0; o.y += v1; *p = o; }
                else          { *p = make_float2(v0, v1); }
            }
        }
    }
}

// ---------------- softmax(K over N) fused with kv = ksm^T @ v per (b,h) ----------------
__global__ void kv_kernel(const float* __restrict__ qkv, float* __restrict__ kvout, int Nn) {
    int bh = blockIdx.x;
    int b = bh >> 3, h = bh & 7;
    int tid = threadIdx.x, ch = tid & 63, grp = tid >> 6;
    const float* base = qkv + (size_t)b * Nn * 1536 + h * 64;
    __shared__ float red[4][64];

    float m = -1e30f;
    for (int n = grp; n < Nn; n += 4) m = fmaxf(m, base[(size_t)n * 1536 + 512 + ch]);
    red[grp][ch] = m;
    __syncthreads();
    float mx = fmaxf(fmaxf(red[0][ch], red[1][ch]), fmaxf(red[2][ch], red[3][ch]));
    __syncthreads();
    float s = 0.f;
    for (int n = grp; n < Nn; n += 4) s += expf(base[(size_t)n * 1536 + 512 + ch] - mx);
    red[grp][ch] = s;
    __syncthreads();
    float inv = 1.f / (red[0][ch] + red[1][ch] + red[2][ch] + red[3][ch]);

    float acc[16];
    #pragma unroll
    for (int i = 0; i < 16; i++) acc[i] = 0.f;
    int ka = grp * 16, cv = ch;
    __shared__ float ws[4][64];
    __shared__ float vs[4][64];
    int nIter = (Nn + 3) >> 2;
    for (int it = 0; it < nIter; it++) {
        int n = it * 4 + grp;
        float kw = 0.f, vv = 0.f;
        if (n < Nn) {
            kw = expf(base[(size_t)n * 1536 + 512 + ch] - mx) * inv;
            vv = base[(size_t)n * 1536 + 1024 + ch];
        }
        __syncthreads();
        ws[grp][ch] = kw; vs[grp][ch] = vv;
        __syncthreads();
        float v0 = vs[0][cv], v1 = vs[1][cv], v2 = vs[2][cv], v3 = vs[3][cv];
        #pragma unroll
        for (int i = 0; i < 16; i++)
            acc[i] += ws[0][ka+i]*v0 + ws[1][ka+i]*v1 + ws[2][ka+i]*v2 + ws[3][ka+i]*v3;
    }
    float* kvp = kvout + ((size_t)bh * 64 + ka) * 64 + cv;
    #pragma unroll
    for (int i = 0; i < 16; i++) kvp[(size_t)i * 64] = acc[i];
}

// ---------------- CRPE depthwise conv on V image (3x3 / 5x5 / 7x7 per head group) ----------------
__global__ void crpe_conv_kernel(const float* __restrict__ qkv, float* __restrict__ convout,
                                 const float* __restrict__ w3, const float* __restrict__ b3,
                                 const float* __restrict__ w5, const float* __restrict__ b5,
                                 const float* __restrict__ w7, const float* __restrict__ b7,
                                 int Nn, int H, int W) {
    size_t idx = (size_t)blockIdx.x * blockDim.x + threadIdx.x;
    int HW = H * W;
    size_t total = (size_t)Bsz * HW * Csz;
    if (idx >= total) return;
    int c = (int)(idx & (Csz-1));
    size_t t = idx >> 9;
    int p = (int)(t % HW);
    int b = (int)(t / HW);
    int h = c >> 6;
    int ks; const float* wp; float acc;
    if (h < 2)      { ks = 3; wp = w3 + c * 9;          acc = b3[c];       }
    else if (h < 5) { ks = 5; wp = w5 + (c - 128) * 25; acc = b5[c - 128]; }
    else            { ks = 7; wp = w7 + (c - 320) * 49; acc = b7[c - 320]; }
    int y = p / W, x = p % W, r = ks >> 1;
    const float* vbase = qkv + (size_t)b * Nn * 1536 + 1024 + c;
    for (int dy = -r; dy <= r; dy++) {
        int yy = y + dy;
        if ((unsigned)yy >= (unsigned)H) continue;
        for (int dx = -r; dx <= r; dx++) {
            int xc = x + dx;
            if ((unsigned)xc >= (unsigned)W) continue;
            acc += wp[(dy+r)*ks + (dx+r)] * vbase[(size_t)(1 + yy*W + xc) * 1536];
        }
    }
    convout[idx] = acc;
}

// ---------------- fa = q @ kv, o = SCALE*fa + q*conv (crpe); output rounded to tf32 ----------------
__global__ void fa_kernel(const float* __restrict__ qkv, const float* __restrict__ kvbuf,
                          const float* __restrict__ conv, float* __restrict__ obuf,
                          int Nn, int HW) {
    int bh = blockIdx.x;
    int b = bh >> 3, h = bh & 7;
    int n0 = blockIdx.y * 32;
    int tid = threadIdx.x, cv = tid & 63, yg = tid >> 6;
    __shared__ float kvs[64][65];
    __shared__ float qs[4][64];
    const float* kvsrc = kvbuf + (size_t)bh * 4096;
    for (int t = tid; t < 4096; t += 256) kvs[t >> 6][t & 63] = kvsrc[t];
    for (int it = 0; it < 8; it++) {
        int n = n0 + it * 4 + yg;
        bool ok = n < Nn;
        __syncthreads();
        qs[yg][cv] = ok ? qkv[((size_t)b * Nn + n) * 1536 + h * 64 + cv] : 0.f;
        __syncthreads();
        if (!ok) continue;
        float acc = 0.f;
        #pragma unroll
        for (int k = 0; k < 64; k++) acc += qs[yg][k] * kvs[k][cv];
        float res = 0.125f * acc;   // SCALE = 64^-0.5
        if (n > 0) res += qs[yg][cv] * conv[((size_t)b * HW + (n - 1)) * Csz + h * 64 + cv];
        obuf[((size_t)b * Nn + n) * Csz + h * 64 + cv] = rtf32(res);
    }
}

// ---------------- cross-scale combine: x = feats + cur_i + interp(cur_A) + interp(cur_B) ----------------
__global__ void combine_kernel(const float* __restrict__ feats, const float* __restrict__ curi,
                               const float* __restrict__ curA, const float* __restrict__ curB,
                               float* __restrict__ xout,
                               int Nout, int Wout,
                               int NA, int WA, int pA,
                               int NB, int WB, int pB) {
    size_t idx = (size_t)blockIdx.x * blockDim.x + threadIdx.x;
    size_t total = (size_t)Bsz * Nout * Csz;
    if (idx >= total) return;
    int c = (int)(idx & (Csz-1));
    size_t t = idx >> 9;
    int n = (int)(t % Nout);
    int b = (int)(t / Nout);
    float val = feats[idx] + curi[idx];
    if (n == 0) {
        val += curA[(size_t)b * NA * Csz + c] + curB[(size_t)b * NB * Csz + c];
    } else {
        int p = n - 1, oy = p / Wout, ox = p % Wout;
        {
            int sy = g_rs_start[pA][oy], ny = g_rs_ntap[pA][oy];
            int sx = g_rs_start[pA][ox], nx = g_rs_ntap[pA][ox];
            float accy = 0.f;
            for (int ty = 0; ty < ny; ty++) {
                const float* rp = curA + ((size_t)b * NA + 1 + (size_t)(sy + ty) * WA + sx) * Csz + c;
                float a2 = 0.f;
                for (int txi = 0; txi < nx; txi++) a2 += g_rs_w[pA][ox][txi] * rp[(size_t)txi * Csz];
                accy += g_rs_w[pA][oy][ty] * a2;
            }
            val += accy;
        }
        {
            int sy = g_rs_start[pB][oy], ny = g_rs_ntap[pB][oy];
            int sx = g_rs_start[pB][ox], nx = g_rs_ntap[pB][ox];
            float accy = 0.f;
            for (int ty = 0; ty < ny; ty++) {
                const float* rp = curB + ((size_t)b * NB + 1 + (size_t)(sy + ty) * WB + sx) * Csz + c;
                float a2 = 0.f;
                for (int txi = 0; txi < nx; txi++) a2 += g_rs_w[pB][ox][txi] * rp[(size_t)txi * Csz];
                accy += g_rs_w[pB][oy][ty] * a2;
            }
            val += accy;
        }
    }
    xout[idx] = val;
}

// ---------------- host orchestration ----------------
extern "C" void kernel_launch(void* const* d_in, const int* in_sizes, int n_in,
                              void* d_out, int out_size) {
    const float* x[3] = {(const float*)d_in[0], (const float*)d_in[1], (const float*)d_in[2]};
    const float* cpe_w  = (const float*)d_in[3];
    const float* cpe_b  = (const float*)d_in[4];
    const float* n1_g   = (const float*)d_in[5];
    const float* n1_b   = (const float*)d_in[6];
    const float* n2_g   = (const float*)d_in[7];
    const float* n2_b   = (const float*)d_in[8];
    const float* qkv_w  = (const float*)d_in[9];
    const float* proj_w = (const float*)d_in[10];
    const float* proj_b = (const float*)d_in[11];
    const float* w3 = (const float*)d_in[12];
    const float* b3 = (const float*)d_in[13];
    const float* w5 = (const float*)d_in[14];
    const float* b5 = (const float*)d_in[15];
    const float* w7 = (const float*)d_in[16];
    const float* b7 = (const float*)d_in[17];
    const float* fc1_w = (const float*)d_in[18];
    const float* fc1_b = (const float*)d_in[19];
    const float* fc2_w = (const float*)d_in[20];
    const float* fc2_b = (const float*)d_in[21];
    float* out = (float*)d_out;

    float *xp, *ln, *qkv, *conv, *obuf, *kv, *cur, *hid, *wbuf;
    cudaGetSymbolAddress((void**)&xp,  g_xp);
    cudaGetSymbolAddress((void**)&ln,  g_ln);
    cudaGetSymbolAddress((void**)&qkv, g_qkv);
    cudaGetSymbolAddress((void**)&conv,g_conv);
    cudaGetSymbolAddress((void**)&obuf,g_o);
    cudaGetSymbolAddress((void**)&kv,  g_kv);
    cudaGetSymbolAddress((void**)&cur, g_cur);
    cudaGetSymbolAddress((void**)&hid, g_hid);
    cudaGetSymbolAddress((void**)&wbuf,g_wbuf);

    const int SM_GEMM = (2 * 128 * AST + 2 * 32 * BST) * 4;   // 71680 B
    static bool attr_done = false;
    if (!attr_done) {
        cudaFuncSetAttribute(gemm_tc, cudaFuncAttributeMaxDynamicSharedMemorySize, SM_GEMM);
        attr_done = true;
    }

    // tf32-rounded weight copies
    float* wq = wbuf;                    // 3*512*1536 = 2359296
    float* wp = wbuf + 2359296;          // 3*512*512  =  786432
    float* w1 = wbuf + 2359296 + 786432; // 512*2048   = 1048576
    float* w2 = w1 + 1048576;            // 2048*512   = 1048576
    round_tf32_kernel<<<(2359296+255)/256,256>>>(qkv_w,  wq, 2359296);
    round_tf32_kernel<<<(786432+255)/256, 256>>>(proj_w, wp, 786432);
    round_tf32_kernel<<<(1048576+255)/256,256>>>(fc1_w,  w1, 1048576);
    round_tf32_kernel<<<(1048576+255)/256,256>>>(fc2_w,  w2, 1048576);

    const int Hh[3] = {56, 28, 14};
    const int Nn[3] = {N0, N1, N2};
    const int Mm[3] = {M0t, M1t, M2t};
    const size_t curoff[3] = {0, (size_t)M0t * Csz, (size_t)(M0t + M1t) * Csz};
    const int pairIdx[3][3] = { {-1, 0, 1}, {2, -1, 3}, {4, 5, -1} };

    resize_init_kernel<<<6, 64>>>();

    // --------- phase A: per-branch attention -> cur ---------
    for (int i = 0; i < 3; i++) {
        int H = Hh[i], W = Hh[i], Ni = Nn[i], Mi = Mm[i], HW = H * W;
        size_t totalMC = (size_t)Mi * Csz;
        int blocks = (int)((totalMC + 255) / 256);

        cpe_kernel<<<blocks, 256>>>(x[i], cpe_w + (size_t)i * Csz * 9, cpe_b + i * Csz,
                                    xp, Ni, H, W);
        ln_kernel<<<Mi, 128>>>(xp, ln, n1_g + i * Csz, n1_b + i * Csz);

        dim3 gq(1536 / 128, (Mi + 127) / 128);
        gemm_tc<<<gq, 256, SM_GEMM>>>(ln, wq + (size_t)i * Csz * 1536, qkv,
                                      Mi, 1536, Csz, nullptr, 0);

        kv_kernel<<<Bsz * NHh, 256>>>(qkv, kv, Ni);

        size_t totConv = (size_t)Bsz * HW * Csz;
        crpe_conv_kernel<<<(int)((totConv + 255) / 256), 256>>>(
            qkv, conv,
            w3 + (size_t)i * 128 * 9,  b3 + i * 128,
            w5 + (size_t)i * 192 * 25, b5 + i * 192,
            w7 + (size_t)i * 192 * 49, b7 + i * 192,
            Ni, H, W);

        dim3 gfa(Bsz * NHh, (Ni + 31) / 32);
        fa_kernel<<<gfa, 256>>>(qkv, kv, conv, obuf, Ni, HW);

        dim3 gp(Csz / 128, (Mi + 127) / 128);
        gemm_tc<<<gp, 256, SM_GEMM>>>(obuf, wp + (size_t)i * Csz * Csz, cur + curoff[i],
                                      Mi, Csz, Csz, proj_b + i * Csz, 1);
    }

    // --------- phase B: cross-scale combine + MLP ---------
    for (int i = 0; i < 3; i++) {
        int Ni = Nn[i], Mi = Mm[i], W = Hh[i];
        int jA = (i == 0) ? 1 : 0;
        int jB = (i == 2) ? 1 : 2;
        size_t totalMC = (size_t)Mi * Csz;
        int blocks = (int)((totalMC + 255) / 256);
        size_t outoff = curoff[i];

        combine_kernel<<<blocks, 256>>>(x[i], cur + curoff[i],
                                        cur + curoff[jA], cur + curoff[jB],
                                        out + outoff,
                                        Ni, W,
                                        Nn[jA], Hh[jA], pairIdx[jA][i],
                                        Nn[jB], Hh[jB], pairIdx[jB][i]);

        ln_kernel<<<Mi, 128>>>(out + outoff, ln, n2_g + i * Csz, n2_b + i * Csz);

        dim3 g1(2048 / 128, (Mi + 127) / 128);
        gemm_tc<<<g1, 256, SM_GEMM>>>(ln, w1, hid, Mi, 2048, Csz, fc1_b, 2);

        dim3 g2(Csz / 128, (Mi + 127) / 128);
        gemm_tc<<<g2, 256, SM_GEMM>>>(hid, w2, out + outoff, Mi, Csz, 2048, fc2_b, 3);
    }
}

// round 5
// speedup vs baseline: 2.5083x; 1.1359x over previous
#include <cuda_runtime.h>
#include <cstdint>
#include <math.h>

// ---------------- problem constants ----------------
#define Csz 512
#define NHh 8
#define CHd 64
#define Bsz 16

#define N0 3137
#define N1 785
#define N2 197
#define M0t (Bsz*N0)     // 50192
#define M1t (Bsz*N1)     // 12560
#define M2t (Bsz*N2)     // 3152
#define MTOT (M0t+M1t+M2t)

#define NSMAX 32         // max N-slices for kv partials (branch0: ceil(3137/128)=25)

// ---------------- scratch (static device memory; no allocation) ----------------
__device__ float g_xp[(size_t)M0t*Csz];
__device__ float g_ln[(size_t)M0t*Csz];
__device__ float g_qkv[(size_t)M0t*3*Csz];
__device__ float g_conv[(size_t)Bsz*56*56*Csz];
__device__ float g_o[(size_t)M0t*Csz];
__device__ float g_kv[Bsz*NHh*64*64];
__device__ float g_cur[(size_t)MTOT*Csz];
__device__ float g_hid[(size_t)M0t*2048];
__device__ float g_wbuf[5242880];   // tf32-rounded TRANSPOSED weights: wq | wp | w1 | w2

// kv softmax scratch
__device__ float g_smax[128*NSMAX*64];
__device__ float g_ssum[128*NSMAX*64];
__device__ float g_mx[128*64];
__device__ float g_inv[128*64];
__device__ float g_kvpart[(size_t)128*NSMAX*4096];

// resize tap tables
__device__ int   g_rs_start[6][56];
__device__ int   g_rs_ntap[6][56];
__device__ float g_rs_w[6][56][8];

// ---------------- helpers ----------------
__device__ __forceinline__ float rtf32(float x) {
    uint32_t u;
    asm("cvt.rna.tf32.f32 %0, %1;" : "=r"(u) : "f"(x));
    return __uint_as_float(u);
}

__device__ __forceinline__ void cp16(void* dst, const void* src) {
    uint32_t d = (uint32_t)__cvta_generic_to_shared(dst);
    asm volatile("cp.async.cg.shared.global [%0], [%1], 16;" :: "r"(d), "l"(src));
}

__device__ __forceinline__ void mma_tf32(float* c, const uint32_t* a, const uint32_t* b) {
    asm volatile(
        "mma.sync.aligned.m16n8k8.row.col.f32.tf32.tf32.f32 "
        "{%0,%1,%2,%3}, {%4,%5,%6,%7}, {%8,%9}, {%0,%1,%2,%3};"
        : "+f"(c[0]), "+f"(c[1]), "+f"(c[2]), "+f"(c[3])
        : "r"(a[0]), "r"(a[1]), "r"(a[2]), "r"(a[3]), "r"(b[0]), "r"(b[1]));
}

// ---------------- weight transpose + tf32 rounding (GEMM B stays [K][N]) ----------------
__global__ void round_tf32_kernel(const float* __restrict__ in, float* __restrict__ out, int n) {
    int i = blockIdx.x * blockDim.x + threadIdx.x;
    if (i < n) out[i] = rtf32(in[i]);
}

// ---------------- resize weight init (exact jax.image.resize bilinear, antialias=True) ----------------
__global__ void resize_init_kernel() {
    const int ins[6]  = {56,56,28,28,14,14};
    const int outs[6] = {28,14,56,14,56,28};
    int p = blockIdx.x;
    int o = threadIdx.x;
    int is = ins[p], os = outs[p];
    if (o >= os) return;
    float inv = (float)is / (float)os;
    float ks  = inv > 1.f ? inv : 1.f;
    float sample = (o + 0.5f) * inv - 0.5f;
    float wsum = 0.f;
    for (int i = 0; i < is; i++) {
        float w = 1.f - fabsf(sample - (float)i) / ks;
        if (w > 0.f) wsum += w;
    }
    int st = -1, cnt = 0;
    for (int i = 0; i < is; i++) {
        float w = 1.f - fabsf(sample - (float)i) / ks;
        if (w > 0.f) {
            if (st < 0) st = i;
            if (cnt < 8) g_rs_w[p][o][cnt] = w / wsum;
            cnt++;
        }
    }
    for (int j = cnt; j < 8; j++) g_rs_w[p][o][j] = 0.f;
    g_rs_start[p][o] = (st < 0) ? 0 : st;
    g_rs_ntap[p][o]  = (cnt > 8) ? 8 : cnt;
}

// ---------------- CPE: depthwise 3x3 conv + bias + residual, cls passthrough ----------------
__global__ void cpe_kernel(const float* __restrict__ x, const float* __restrict__ w,
                           const float* __restrict__ bias, float* __restrict__ xp,
                           int Nn, int H, int W) {
    size_t idx = (size_t)blockIdx.x * blockDim.x + threadIdx.x;
    size_t total = (size_t)Bsz * Nn * Csz;
    if (idx >= total) return;
    int c = (int)(idx & (Csz-1));
    size_t t = idx >> 9;
    int n = (int)(t % Nn);
    int b = (int)(t / Nn);
    const float* xb = x + (size_t)b * Nn * Csz;
    float val = xb[(size_t)n * Csz + c];
    if (n == 0) { xp[idx] = val; return; }
    int p = n - 1, y = p / W, xx = p % W;
    float acc = bias[c] + val;
    const float* wc = w + c * 9;
    #pragma unroll
    for (int dy = -1; dy <= 1; dy++) {
        int yy = y + dy;
        if ((unsigned)yy >= (unsigned)H) continue;
        #pragma unroll
        for (int dx = -1; dx <= 1; dx++) {
            int xc = xx + dx;
            if ((unsigned)xc >= (unsigned)W) continue;
            acc += wc[(dy+1)*3 + (dx+1)] * xb[(size_t)(1 + yy*W + xc) * Csz + c];
        }
    }
    xp[idx] = acc;
}

// ---------------- LayerNorm over C=512 (output rounded to tf32 — feeds GEMM) ----------------
__global__ void ln_kernel(const float* __restrict__ in, float* __restrict__ out,
                          const float* __restrict__ g, const float* __restrict__ beta) {
    size_t row = blockIdx.x;
    const float4* p = (const float4*)(in + row * Csz);
    float4 v = p[threadIdx.x];
    float s = v.x + v.y + v.z + v.w;
    #pragma unroll
    for (int o = 16; o; o >>= 1) s += __shfl_xor_sync(0xffffffffu, s, o);
    __shared__ float sh[4];
    __shared__ float sh2[4];
    if ((threadIdx.x & 31) == 0) sh[threadIdx.x >> 5] = s;
    __syncthreads();
    float mean = (sh[0] + sh[1] + sh[2] + sh[3]) * (1.f/512.f);
    float dx = v.x - mean, dy = v.y - mean, dz = v.z - mean, dw = v.w - mean;
    float q = dx*dx + dy*dy + dz*dz + dw*dw;
    #pragma unroll
    for (int o = 16; o; o >>= 1) q += __shfl_xor_sync(0xffffffffu, q, o);
    if ((threadIdx.x & 31) == 0) sh2[threadIdx.x >> 5] = q;
    __syncthreads();
    float var = (sh2[0] + sh2[1] + sh2[2] + sh2[3]) * (1.f/512.f);
    float rs = rsqrtf(var + 1e-5f);
    float4 gg = ((const float4*)g)[threadIdx.x];
    float4 bb = ((const float4*)beta)[threadIdx.x];
    float4 r;
    r.x = rtf32(dx * rs * gg.x + bb.x);
    r.y = rtf32(dy * rs * gg.y + bb.y);
    r.z = rtf32(dz * rs * gg.z + bb.z);
    r.w = rtf32(dw * rs * gg.w + bb.w);
    ((float4*)(out + row * Csz))[threadIdx.x] = r;
}

// ---------------- tensor-core tf32 GEMM 128x128x32, 3-stage cp.async pipeline ----------------
// epi: 0 = store, 1 = +bias store, 2 = +bias gelu store(rounded), 3 = out += acc + bias
#define AST 36
#define BST 136
#define ASZ (128*AST)    // floats per A stage (4608)
#define BSZ (32*BST)     // floats per B stage (4352)
#define SM_GEMM (3*(ASZ+BSZ)*4)   // 107520 B
__global__ __launch_bounds__(256) void gemm_tc(
        const float* __restrict__ A, const float* __restrict__ B,
        float* __restrict__ Co, int M, int N, int K,
        const float* __restrict__ bias, int epi) {
    extern __shared__ float smbuf[];
    float* As = smbuf;             // 3 stages
    float* Bs = smbuf + 3 * ASZ;   // 3 stages
    int tid = threadIdx.x;
    int bm = blockIdx.y * 128, bn = blockIdx.x * 128;
    int wid = tid >> 5, lane = tid & 31;
    int g = lane >> 2, t = lane & 3;
    int warpM = wid >> 2, warpN = wid & 3;
    int mBase = warpM * 64, nBase = warpN * 32;

    float acc[4][4][4];
    #pragma unroll
    for (int i = 0; i < 4; i++)
        #pragma unroll
        for (int j = 0; j < 4; j++)
            #pragma unroll
            for (int r = 0; r < 4; r++) acc[i][j][r] = 0.f;

    int KT = K >> 5;

    auto issue = [&](int stage, int kt) {
        float* as = As + stage * ASZ;
        float* bs = Bs + stage * BSZ;
        #pragma unroll
        for (int q = 0; q < 4; q++) {
            int c = tid + q * 256;
            int r = c >> 3, k4 = (c & 7) << 2;
            int rr = bm + r; if (rr > M - 1) rr = M - 1;
            cp16(as + r * AST + k4, A + (size_t)rr * K + kt * 32 + k4);
        }
        #pragma unroll
        for (int q = 0; q < 4; q++) {
            int c = tid + q * 256;
            int r = c >> 5, n4 = (c & 31) << 2;
            cp16(bs + r * BST + n4, B + (size_t)(kt * 32 + r) * N + bn + n4);
        }
        asm volatile("cp.async.commit_group;");
    };

    auto compute = [&](int stage) {
        const float* as = As + stage * ASZ;
        const float* bs = Bs + stage * BSZ;
        #pragma unroll
        for (int ks = 0; ks < 4; ks++) {
            int k0 = ks * 8 + t;
            uint32_t af[4][4], bf[4][2];
            #pragma unroll
            for (int i = 0; i < 4; i++) {
                const float* ap = as + (mBase + 16 * i + g) * AST;
                af[i][0] = __float_as_uint(ap[k0]);
                af[i][1] = __float_as_uint(ap[8 * AST + k0]);
                af[i][2] = __float_as_uint(ap[k0 + 4]);
                af[i][3] = __float_as_uint(ap[8 * AST + k0 + 4]);
            }
            #pragma unroll
            for (int j = 0; j < 4; j++) {
                const float* bp = bs + k0 * BST + nBase + 8 * j + g;
                bf[j][0] = __float_as_uint(bp[0]);
                bf[j][1] = __float_as_uint(bp[4 * BST]);
            }
            #pragma unroll
            for (int i = 0; i < 4; i++)
                #pragma unroll
                for (int j = 0; j < 4; j++)
                    mma_tf32(acc[i][j], af[i], bf[j]);
        }
    };

    issue(0, 0);
    if (KT > 1) issue(1, 1);
    int stage = 0;
    for (int kt = 0; kt < KT; kt++) {
        if (kt + 2 < KT) issue((kt + 2) % 3, kt + 2);
        if (kt + 2 < KT)      asm volatile("cp.async.wait_group 2;");
        else if (kt + 1 < KT) asm volatile("cp.async.wait_group 1;");
        else                  asm volatile("cp.async.wait_group 0;");
        __syncthreads();
        compute(stage);
        __syncthreads();
        stage = (stage + 1) % 3;
    }

    // epilogue
    #pragma unroll
    for (int i = 0; i < 4; i++) {
        #pragma unroll
        for (int half = 0; half < 2; half++) {
            int row = bm + mBase + 16 * i + g + half * 8;
            if (row >= M) continue;
            #pragma unroll
            for (int j = 0; j < 4; j++) {
                int col = bn + nBase + 8 * j + 2 * t;
                float v0 = acc[i][j][half * 2 + 0];
                float v1 = acc[i][j][half * 2 + 1];
                if (epi >= 1) { v0 += bias[col]; v1 += bias[col + 1]; }
                if (epi == 2) {
                    v0 = rtf32(0.5f * v0 * (1.f + erff(v0 * 0.70710678118654752f)));
                    v1 = rtf32(0.5f * v1 * (1.f + erff(v1 * 0.70710678118654752f)));
                }
                float2* p = (float2*)(Co + (size_t)row * N + col);
                if (epi == 3) { float2 o = *p; o.x += v0; o.y += v1; *p = o; }
                else          { *p = make_float2(v0, v1); }
            }
        }
    }
}

// ---------------- kv phase 1: per-slice online max + sumexp over K channel columns ----------------
__global__ void kv_reduce_kernel(const float* __restrict__ qkv, int Nn) {
    int bh = blockIdx.x, sl = blockIdx.y;
    int b = bh >> 3, h = bh & 7;
    int tid = threadIdx.x, ch = tid & 63, grp = tid >> 6;
    const float* base = qkv + (size_t)b * Nn * 1536 + h * 64 + 512;
    int n0 = sl * 128;
    int n1 = n0 + 128; if (n1 > Nn) n1 = Nn;
    float m = -1e30f, s = 0.f;
    for (int n = n0 + grp; n < n1; n += 4) {
        float t = base[(size_t)n * 1536 + ch];
        float mn = fmaxf(m, t);
        s = s * expf(m - mn) + expf(t - mn);
        m = mn;
    }
    __shared__ float rm[4][64];
    __shared__ float rs[4][64];
    rm[grp][ch] = m; rs[grp][ch] = s;
    __syncthreads();
    if (tid < 64) {
        float gm = fmaxf(fmaxf(rm[0][ch], rm[1][ch]), fmaxf(rm[2][ch], rm[3][ch]));
        float gs = rs[0][ch] * expf(rm[0][ch] - gm) + rs[1][ch] * expf(rm[1][ch] - gm)
                 + rs[2][ch] * expf(rm[2][ch] - gm) + rs[3][ch] * expf(rm[3][ch] - gm);
        g_smax[((size_t)bh * NSMAX + sl) * 64 + ch] = gm;
        g_ssum[((size_t)bh * NSMAX + sl) * 64 + ch] = gs;
    }
}

// ---------------- kv phase 2: combine slices -> global max + 1/sum ----------------
__global__ void kv_combine_kernel(int NS) {
    int bh = blockIdx.x, ch = threadIdx.x;
    float gm = -1e30f;
    for (int s = 0; s < NS; s++)
        gm = fmaxf(gm, g_smax[((size_t)bh * NSMAX + s) * 64 + ch]);
    float S = 0.f;
    for (int s = 0; s < NS; s++)
        S += g_ssum[((size_t)bh * NSMAX + s) * 64 + ch]
           * expf(g_smax[((size_t)bh * NSMAX + s) * 64 + ch] - gm);
    g_mx[bh * 64 + ch] = gm;
    g_inv[bh * 64 + ch] = 1.f / S;
}

// ---------------- kv phase 3: per-slice partial kv = ksm^T @ v ----------------
__global__ void kv_partial_kernel(const float* __restrict__ qkv, int Nn) {
    int bh = blockIdx.x, sl = blockIdx.y;
    int b = bh >> 3, h = bh & 7;
    int tid = threadIdx.x, ch = tid & 63, grp = tid >> 6;
    const float* base = qkv + (size_t)b * Nn * 1536 + h * 64;
    float mx = g_mx[bh * 64 + ch];
    float inv = g_inv[bh * 64 + ch];
    int n0 = sl * 128;
    int n1 = n0 + 128; if (n1 > Nn) n1 = Nn;

    float acc[16];
    #pragma unroll
    for (int i = 0; i < 16; i++) acc[i] = 0.f;
    int ka = grp * 16, cv = ch;
    __shared__ float ws[4][64];
    __shared__ float vs[4][64];
    for (int it = 0; it < 32; it++) {
        int n = n0 + it * 4 + grp;
        float kw = 0.f, vv = 0.f;
        if (n < n1) {
            kw = expf(base[(size_t)n * 1536 + 512 + ch] - mx) * inv;
            vv = base[(size_t)n * 1536 + 1024 + ch];
        }
        __syncthreads();
        ws[grp][ch] = kw; vs[grp][ch] = vv;
        __syncthreads();
        float v0 = vs[0][cv], v1 = vs[1][cv], v2 = vs[2][cv], v3 = vs[3][cv];
        #pragma unroll
        for (int i = 0; i < 16; i++)
            acc[i] += ws[0][ka+i]*v0 + ws[1][ka+i]*v1 + ws[2][ka+i]*v2 + ws[3][ka+i]*v3;
    }
    float* kvp = g_kvpart + ((size_t)bh * NSMAX + sl) * 4096 + (size_t)ka * 64 + cv;
    #pragma unroll
    for (int i = 0; i < 16; i++) kvp[(size_t)i * 64] = acc[i];
}

// ---------------- kv phase 4: fixed-order slice reduction (deterministic) ----------------
__global__ void kv_final_kernel(float* __restrict__ kvout, int NS) {
    int idx = blockIdx.x * blockDim.x + threadIdx.x;   // 128*4096
    int bh = idx >> 12, off = idx & 4095;
    float s = 0.f;
    for (int sl = 0; sl < NS; sl++)
        s += g_kvpart[((size_t)bh * NSMAX + sl) * 4096 + off];
    kvout[idx] = s;
}

// ---------------- CRPE depthwise conv on V image ----------------
__global__ void crpe_conv_kernel(const float* __restrict__ qkv, float* __restrict__ convout,
                                 const float* __restrict__ w3, const float* __restrict__ b3,
                                 const float* __restrict__ w5, const float* __restrict__ b5,
                                 const float* __restrict__ w7, const float* __restrict__ b7,
                                 int Nn, int H, int W) {
    size_t idx = (size_t)blockIdx.x * blockDim.x + threadIdx.x;
    int HW = H * W;
    size_t total = (size_t)Bsz * HW * Csz;
    if (idx >= total) return;
    int c = (int)(idx & (Csz-1));
    size_t t = idx >> 9;
    int p = (int)(t % HW);
    int b = (int)(t / HW);
    int h = c >> 6;
    int ks; const float* wp; float acc;
    if (h < 2)      { ks = 3; wp = w3 + c * 9;          acc = b3[c];       }
    else if (h < 5) { ks = 5; wp = w5 + (c - 128) * 25; acc = b5[c - 128]; }
    else            { ks = 7; wp = w7 + (c - 320) * 49; acc = b7[c - 320]; }
    int y = p / W, x = p % W, r = ks >> 1;
    const float* vbase = qkv + (size_t)b * Nn * 1536 + 1024 + c;
    for (int dy = -r; dy <= r; dy++) {
        int yy = y + dy;
        if ((unsigned)yy >= (unsigned)H) continue;
        for (int dx = -r; dx <= r; dx++) {
            int xc = x + dx;
            if ((unsigned)xc >= (unsigned)W) continue;
            acc += wp[(dy+r)*ks + (dx+r)] * vbase[(size_t)(1 + yy*W + xc) * 1536];
        }
    }
    convout[idx] = acc;
}

// ---------------- fa = q @ kv, o = SCALE*fa + q*conv; output rounded to tf32 ----------------
__global__ void fa_kernel(const float* __restrict__ qkv, const float* __restrict__ kvbuf,
                          const float* __restrict__ conv, float* __restrict__ obuf,
                          int Nn, int HW) {
    int bh = blockIdx.x;
    int b = bh >> 3, h = bh & 7;
    int n0 = blockIdx.y * 32;
    int tid = threadIdx.x, cv = tid & 63, yg = tid >> 6;
    __shared__ float kvs[64][65];
    __shared__ float qs[4][64];
    const float* kvsrc = kvbuf + (size_t)bh * 4096;
    for (int t = tid; t < 4096; t += 256) kvs[t >> 6][t & 63] = kvsrc[t];
    for (int it = 0; it < 8; it++) {
        int n = n0 + it * 4 + yg;
        bool ok = n < Nn;
        __syncthreads();
        qs[yg][cv] = ok ? qkv[((size_t)b * Nn + n) * 1536 + h * 64 + cv] : 0.f;
        __syncthreads();
        if (!ok) continue;
        float acc = 0.f;
        #pragma unroll
        for (int k = 0; k < 64; k++) acc += qs[yg][k] * kvs[k][cv];
        float res = 0.125f * acc;
        if (n > 0) res += qs[yg][cv] * conv[((size_t)b * HW + (n - 1)) * Csz + h * 64 + cv];
        obuf[((size_t)b * Nn + n) * Csz + h * 64 + cv] = rtf32(res);
    }
}

// ---------------- cross-scale combine ----------------
__global__ void combine_kernel(const float* __restrict__ feats, const float* __restrict__ curi,
                               const float* __restrict__ curA, const float* __restrict__ curB,
                               float* __restrict__ xout,
                               int Nout, int Wout,
                               int NA, int WA, int pA,
                               int NB, int WB, int pB) {
    size_t idx = (size_t)blockIdx.x * blockDim.x + threadIdx.x;
    size_t total = (size_t)Bsz * Nout * Csz;
    if (idx >= total) return;
    int c = (int)(idx & (Csz-1));
    size_t t = idx >> 9;
    int n = (int)(t % Nout);
    int b = (int)(t / Nout);
    float val = feats[idx] + curi[idx];
    if (n == 0) {
        val += curA[(size_t)b * NA * Csz + c] + curB[(size_t)b * NB * Csz + c];
    } else {
        int p = n - 1, oy = p / Wout, ox = p % Wout;
        {
            int sy = g_rs_start[pA][oy], ny = g_rs_ntap[pA][oy];
            int sx = g_rs_start[pA][ox], nx = g_rs_ntap[pA][ox];
            float accy = 0.f;
            for (int ty = 0; ty < ny; ty++) {
                const float* rp = curA + ((size_t)b * NA + 1 + (size_t)(sy + ty) * WA + sx) * Csz + c;
                float a2 = 0.f;
                for (int txi = 0; txi < nx; txi++) a2 += g_rs_w[pA][ox][txi] * rp[(size_t)txi * Csz];
                accy += g_rs_w[pA][oy][ty] * a2;
            }
            val += accy;
        }
        {
            int sy = g_rs_start[pB][oy], ny = g_rs_ntap[pB][oy];
            int sx = g_rs_start[pB][ox], nx = g_rs_ntap[pB][ox];
            float accy = 0.f;
            for (int ty = 0; ty < ny; ty++) {
                const float* rp = curB + ((size_t)b * NB + 1 + (size_t)(sy + ty) * WB + sx) * Csz + c;
                float a2 = 0.f;
                for (int txi = 0; txi < nx; txi++) a2 += g_rs_w[pB][ox][txi] * rp[(size_t)txi * Csz];
                accy += g_rs_w[pB][oy][ty] * a2;
            }
            val += accy;
        }
    }
    xout[idx] = val;
}

// ---------------- host orchestration ----------------
extern "C" void kernel_launch(void* const* d_in, const int* in_sizes, int n_in,
                              void* d_out, int out_size) {
    const float* x[3] = {(const float*)d_in[0], (const float*)d_in[1], (const float*)d_in[2]};
    const float* cpe_w  = (const float*)d_in[3];
    const float* cpe_b  = (const float*)d_in[4];
    const float* n1_g   = (const float*)d_in[5];
    const float* n1_b   = (const float*)d_in[6];
    const float* n2_g   = (const float*)d_in[7];
    const float* n2_b   = (const float*)d_in[8];
    const float* qkv_w  = (const float*)d_in[9];
    const float* proj_w = (const float*)d_in[10];
    const float* proj_b = (const float*)d_in[11];
    const float* w3 = (const float*)d_in[12];
    const float* b3 = (const float*)d_in[13];
    const float* w5 = (const float*)d_in[14];
    const float* b5 = (const float*)d_in[15];
    const float* w7 = (const float*)d_in[16];
    const float* b7 = (const float*)d_in[17];
    const float* fc1_w = (const float*)d_in[18];
    const float* fc1_b = (const float*)d_in[19];
    const float* fc2_w = (const float*)d_in[20];
    const float* fc2_b = (const float*)d_in[21];
    float* out = (float*)d_out;

    float *xp, *ln, *qkv, *conv, *obuf, *kv, *cur, *hid, *wbuf;
    cudaGetSymbolAddress((void**)&xp,  g_xp);
    cudaGetSymbolAddress((void**)&ln,  g_ln);
    cudaGetSymbolAddress((void**)&qkv, g_qkv);
    cudaGetSymbolAddress((void**)&conv,g_conv);
    cudaGetSymbolAddress((void**)&obuf,g_o);
    cudaGetSymbolAddress((void**)&kv,  g_kv);
    cudaGetSymbolAddress((void**)&cur, g_cur);
    cudaGetSymbolAddress((void**)&hid, g_hid);
    cudaGetSymbolAddress((void**)&wbuf,g_wbuf);

    cudaFuncSetAttribute(gemm_tc, cudaFuncAttributeMaxDynamicSharedMemorySize, SM_GEMM);

    // tf32-rounded weight copies (B layout stays [K][N])
    float* wq = wbuf;                    // 3*512*1536
    float* wp = wbuf + 2359296;          // 3*512*512
    float* w1 = wbuf + 2359296 + 786432; // 512*2048
    float* w2 = w1 + 1048576;            // 2048*512
    round_tf32_kernel<<<(2359296+255)/256,256>>>(qkv_w,  wq, 2359296);
    round_tf32_kernel<<<(786432+255)/256, 256>>>(proj_w, wp, 786432);
    round_tf32_kernel<<<(1048576+255)/256,256>>>(fc1_w,  w1, 1048576);
    round_tf32_kernel<<<(1048576+255)/256,256>>>(fc2_w,  w2, 1048576);

    const int Hh[3] = {56, 28, 14};
    const int Nn[3] = {N0, N1, N2};
    const int Mm[3] = {M0t, M1t, M2t};
    const size_t curoff[3] = {0, (size_t)M0t * Csz, (size_t)(M0t + M1t) * Csz};
    const int pairIdx[3][3] = { {-1, 0, 1}, {2, -1, 3}, {4, 5, -1} };

    resize_init_kernel<<<6, 64>>>();

    // --------- phase A: per-branch attention -> cur ---------
    for (int i = 0; i < 3; i++) {
        int H = Hh[i], W = Hh[i], Ni = Nn[i], Mi = Mm[i], HW = H * W;
        size_t totalMC = (size_t)Mi * Csz;
        int blocks = (int)((totalMC + 255) / 256);
        int NS = (Ni + 127) / 128;

        cpe_kernel<<<blocks, 256>>>(x[i], cpe_w + (size_t)i * Csz * 9, cpe_b + i * Csz,
                                    xp, Ni, H, W);
        ln_kernel<<<Mi, 128>>>(xp, ln, n1_g + i * Csz, n1_b + i * Csz);

        dim3 gq(1536 / 128, (Mi + 127) / 128);
        gemm_tc<<<gq, 256, SM_GEMM>>>(ln, wq + (size_t)i * Csz * 1536, qkv,
                                      Mi, 1536, Csz, nullptr, 0);

        kv_reduce_kernel<<<dim3(128, NS), 256>>>(qkv, Ni);
        kv_combine_kernel<<<128, 64>>>(NS);
        kv_partial_kernel<<<dim3(128, NS), 256>>>(qkv, Ni);
        kv_final_kernel<<<(128*4096)/256, 256>>>(kv, NS);

        size_t totConv = (size_t)Bsz * HW * Csz;
        crpe_conv_kernel<<<(int)((totConv + 255) / 256), 256>>>(
            qkv, conv,
            w3 + (size_t)i * 128 * 9,  b3 + i * 128,
            w5 + (size_t)i * 192 * 25, b5 + i * 192,
            w7 + (size_t)i * 192 * 49, b7 + i * 192,
            Ni, H, W);

        dim3 gfa(Bsz * NHh, (Ni + 31) / 32);
        fa_kernel<<<gfa, 256>>>(qkv, kv, conv, obuf, Ni, HW);

        dim3 gp(Csz / 128, (Mi + 127) / 128);
        gemm_tc<<<gp, 256, SM_GEMM>>>(obuf, wp + (size_t)i * Csz * Csz, cur + curoff[i],
                                      Mi, Csz, Csz, proj_b + i * Csz, 1);
    }

    // --------- phase B: cross-scale combine + MLP ---------
    for (int i = 0; i < 3; i++) {
        int Ni = Nn[i], Mi = Mm[i], W = Hh[i];
        int jA = (i == 0) ? 1 : 0;
        int jB = (i == 2) ? 1 : 2;
        size_t totalMC = (size_t)Mi * Csz;
        int blocks = (int)((totalMC + 255) / 256);
        size_t outoff = curoff[i];

        combine_kernel<<<blocks, 256>>>(x[i], cur + curoff[i],
                                        cur + curoff[jA], cur + curoff[jB],
                                        out + outoff,
                                        Ni, W,
                                        Nn[jA], Hh[jA], pairIdx[jA][i],
                                        Nn[jB], Hh[jB], pairIdx[jB][i]);

        ln_kernel<<<Mi, 128>>>(out + outoff, ln, n2_g + i * Csz, n2_b + i * Csz);

        dim3 g1(2048 / 128, (Mi + 127) / 128);
        gemm_tc<<<g1, 256, SM_GEMM>>>(ln, w1, hid, Mi, 2048, Csz, fc1_b, 2);

        dim3 g2(Csz / 128, (Mi + 127) / 128);
        gemm_tc<<<g2, 256, SM_GEMM>>>(hid, w2, out + outoff, Mi, Csz, 2048, fc2_b, 3);
    }
}